// round 12
// baseline (speedup 1.0000x reference)
#include <cuda_runtime.h>
#include <cstdint>
#include <math.h>

#define B_   128
#define N_   8
#define LQ   32
#define LD   256
#define D_   128
#define NEGV (-9999.0f)
#define STRD 132                       // padded row stride (floats): conflict-free frag loads

// ---- dynamic smem layout (bytes) ----
#define D_OFF   0                       // D tile: 128 rows x 132 floats (raw fp32) = 67584
#define QH_OFF  67584                   // Q hi tile: 32 x 132 floats (tf32-valued)
#define QL_OFF  84480                   // Q lo tile
#define INV_OFF 101376                  // 128 floats: per-row 1/||d||
#define W_OFF   101888                  // 128 floats: per-warp query maxima
#define ACT_OFF 102400                  // 256 ints: compacted row ids
#define CNT_OFF 103424
#define SMEM_TOTAL 103440               // x2 CTA/SM = 206.9 KB < 228 KB

__device__ float g_scores[2 * N_ * B_];   // [z][n][b]
__device__ unsigned int g_ticket;         // wraps mod 2^32; 2048 per launch

__device__ __forceinline__ uint32_t smem_u32(const void* p) {
    uint32_t a;
    asm("{ .reg .u64 t; cvta.to.shared.u64 t, %1; cvt.u32.u64 %0, t; }" : "=r"(a) : "l"(p));
    return a;
}
__device__ __forceinline__ void cp16(uint32_t dst, const void* src) {
    asm volatile("cp.async.cg.shared.global [%0], [%1], 16;" :: "r"(dst), "l"(src));
}
__device__ __forceinline__ void cp_commit() { asm volatile("cp.async.commit_group;"); }
template<int NN> __device__ __forceinline__ void cp_wait() {
    asm volatile("cp.async.wait_group %0;" :: "n"(NN));
}
__device__ __forceinline__ uint32_t to_tf32(float f) {
    uint32_t r;
    asm("cvt.rna.tf32.f32 %0, %1;" : "=r"(r) : "f"(f));
    return r;
}
// m16n8k8 tf32 MMA (sm_80+ ISA; works on plain compute_100)
__device__ __forceinline__ void mma_tf32(float* c, const uint32_t* a,
                                         uint32_t b0, uint32_t b1) {
    asm volatile(
        "mma.sync.aligned.m16n8k8.row.col.f32.tf32.tf32.f32 "
        "{%0,%1,%2,%3}, {%4,%5,%6,%7}, {%8,%9}, {%0,%1,%2,%3};"
        : "+f"(c[0]), "+f"(c[1]), "+f"(c[2]), "+f"(c[3])
        : "r"(a[0]), "r"(a[1]), "r"(a[2]), "r"(a[3]), "r"(b0), "r"(b1));
}

// ---------------------------------------------------------------------------
// MaxSim + fused KL loss. grid (B, N, 2), 256 threads (8 warps), 2 CTAs/SM.
// 3xTF32 error-compensated MMA (acc = Ah*Bh + Ah*Bl + Al*Bh, rel err ~2^-22).
// 8 warps = 2 q-halves x 4 n-groups; each warp 4 n8 tiles over 128-row chunks.
// Mask compaction + per-warp tile skip (work ~ cnt). Last CTA (global ticket)
// computes the KL(batchmean) loss — no second kernel launch.
// ---------------------------------------------------------------------------
__global__ void __launch_bounds__(256, 2)
maxsim_mma(const float* __restrict__ q, const float* __restrict__ dcq,
           const float* __restrict__ dorig, const int* __restrict__ mask,
           float* __restrict__ out)
{
    extern __shared__ __align__(16) char smem[];
    const uint32_t sbu = smem_u32(smem);
    float* sD   = (float*)(smem + D_OFF);
    float* sQh  = (float*)(smem + QH_OFF);
    float* sQl  = (float*)(smem + QL_OFF);
    float* sInv = (float*)(smem + INV_OFF);
    float* sW   = (float*)(smem + W_OFF);
    int*   sAct = (int*)(smem + ACT_OFF);
    int*   sCnt = (int*)(smem + CNT_OFF);
    __shared__ unsigned int sTk;

    const int b = blockIdx.x, n = blockIdx.y, z = blockIdx.z;
    const int t = threadIdx.x, lane = t & 31, w = t >> 5;
    const int wq = w & 1, wn = w >> 1;          // q-half, n-group (32 rows)
    const int g = lane >> 2, tg = lane & 3;
    const float* __restrict__ dpair = (z ? dorig : dcq) + (size_t)(n * B_ + b) * (LD * D_);

    if (t == 0) *sCnt = 0;

    // ---- stage Q: fp32 normalize, split hi/lo, store padded rows ----
    {
        const float4* qb = (const float4*)(q + (size_t)b * LQ * D_);
#pragma unroll
        for (int it = 0; it < 4; it++) {
            int row = it * 8 + w;
            float4 v = qb[row * 32 + lane];
            float ss = v.x * v.x + v.y * v.y + v.z * v.z + v.w * v.w;
#pragma unroll
            for (int o = 16; o; o >>= 1) ss += __shfl_xor_sync(~0u, ss, o);
            float inv = 1.0f / fmaxf(sqrtf(ss), 1e-12f);
            v.x *= inv; v.y *= inv; v.z *= inv; v.w *= inv;
            float4 hi, lo;
            hi.x = __uint_as_float(to_tf32(v.x)); lo.x = __uint_as_float(to_tf32(v.x - hi.x));
            hi.y = __uint_as_float(to_tf32(v.y)); lo.y = __uint_as_float(to_tf32(v.y - hi.y));
            hi.z = __uint_as_float(to_tf32(v.z)); lo.z = __uint_as_float(to_tf32(v.z - hi.z));
            hi.w = __uint_as_float(to_tf32(v.w)); lo.w = __uint_as_float(to_tf32(v.w - hi.w));
            *(float4*)(sQh + row * STRD + lane * 4) = hi;
            *(float4*)(sQl + row * STRD + lane * 4) = lo;
        }
    }
    __syncthreads();

    // ---- mask compaction (order irrelevant: max is commutative) ----
    if (mask[(n * B_ + b) * LD + t]) sAct[atomicAdd(sCnt, 1)] = t;
    __syncthreads();
    const int cnt = *sCnt;

    if (cnt > 0) {
        const int nch = (cnt + 127) >> 7;       // 1 or 2
        const int aoff = (16 * wq + g) * STRD + tg;
        const float* Ah = sQh + aoff;
        const float* Al = sQl + aoff;
        float mx0 = -1e30f, mx1 = -1e30f;

        for (int ch = 0; ch < nch; ch++) {
            const int lcnt = min(cnt - ch * 128, 128);
            if (ch) __syncthreads();             // prior reads done before overwrite

            // ---- load 128 rows (tail duplicates a valid row -> L2 hits) ----
#pragma unroll
            for (int it = 0; it < 16; it++) {
                int row = it * 8 + w;
                int idx = ch * 128 + row; if (idx >= cnt) idx = cnt - 1;
                cp16(sbu + (uint32_t)((row * STRD + lane * 4) * 4),
                     dpair + (size_t)sAct[idx] * D_ + lane * 4);
            }
            cp_commit();
            cp_wait<0>();
            __syncthreads();

            // ---- per-row inverse norms (fp32 exact) ----
#pragma unroll
            for (int rr = 0; rr < 16; rr++) {
                int row = w * 16 + rr;
                float4 v = *(const float4*)(sD + row * STRD + lane * 4);
                float ss = v.x * v.x + v.y * v.y + v.z * v.z + v.w * v.w;
#pragma unroll
                for (int o = 16; o; o >>= 1) ss += __shfl_xor_sync(~0u, ss, o);
                if (lane == 0) sInv[row] = 1.0f / fmaxf(sqrtf(ss), 1e-12f);
            }
            __syncthreads();

            // ---- 3xTF32 MMA: 16 k-steps, up to 4 n8 tiles (skip beyond lcnt) ----
            const int jmax = (lcnt > 32 * wn) ? min(4, (lcnt - 32 * wn + 7) >> 3) : 0;
            float acc[4][4] = {};
            const float* Brow = sD + (32 * wn + g) * STRD + tg;

#pragma unroll
            for (int s = 0; s < 16; s++) {
                const int k0 = 8 * s;
                uint32_t ah[4], al[4];
                ah[0] = __float_as_uint(Ah[k0]);
                ah[1] = __float_as_uint(Ah[8 * STRD + k0]);
                ah[2] = __float_as_uint(Ah[k0 + 4]);
                ah[3] = __float_as_uint(Ah[8 * STRD + k0 + 4]);
                al[0] = __float_as_uint(Al[k0]);
                al[1] = __float_as_uint(Al[8 * STRD + k0]);
                al[2] = __float_as_uint(Al[k0 + 4]);
                al[3] = __float_as_uint(Al[8 * STRD + k0 + 4]);
#pragma unroll
                for (int j = 0; j < 4; j++) {
                    if (j < jmax) {
                        const float* Bp = Brow + j * (8 * STRD);
                        float b0 = Bp[k0], b1 = Bp[k0 + 4];
                        uint32_t b0h = to_tf32(b0), b1h = to_tf32(b1);
                        uint32_t b0l = to_tf32(b0 - __uint_as_float(b0h));
                        uint32_t b1l = to_tf32(b1 - __uint_as_float(b1h));
                        mma_tf32(acc[j], ah, b0h, b1h);
                        mma_tf32(acc[j], ah, b0l, b1l);
                        mma_tf32(acc[j], al, b0h, b1h);
                    }
                }
            }

            // ---- epilogue: scale by 1/||d||, fold into running per-query max ----
#pragma unroll
            for (int j = 0; j < 4; j++) {
                if (j < jmax) {
                    float2 iv = *(const float2*)(sInv + 32 * wn + 8 * j + 2 * tg);
                    mx0 = fmaxf(mx0, fmaxf(acc[j][0] * iv.x, acc[j][1] * iv.y));
                    mx1 = fmaxf(mx1, fmaxf(acc[j][2] * iv.x, acc[j][3] * iv.y));
                }
            }
        }

        // ---- reduce: max over lanes sharing a query row, then across warps ----
        mx0 = fmaxf(mx0, __shfl_xor_sync(~0u, mx0, 1));
        mx0 = fmaxf(mx0, __shfl_xor_sync(~0u, mx0, 2));
        mx1 = fmaxf(mx1, __shfl_xor_sync(~0u, mx1, 1));
        mx1 = fmaxf(mx1, __shfl_xor_sync(~0u, mx1, 2));
        if (tg == 0) {
            sW[w * 16 + g]     = mx0;           // query 16*wq + g
            sW[w * 16 + 8 + g] = mx1;           // query +8
        }
        __syncthreads();
        if (t < 32) {
            int wq2 = t >> 4, m = t & 15;       // query t = 16*wq2 + m
            float v = fmaxf(fmaxf(sW[wq2 * 16 + m],       sW[(2 + wq2) * 16 + m]),
                            fmaxf(sW[(4 + wq2) * 16 + m], sW[(6 + wq2) * 16 + m]));
#pragma unroll
            for (int o = 16; o; o >>= 1) v += __shfl_xor_sync(~0u, v, o);
            if (t == 0) g_scores[(z * N_ + n) * B_ + b] = v;
        }
    } else if (t == 0) {                        // all masked: scores = 32 * NEG
        g_scores[(z * N_ + n) * B_ + b] = 32.0f * NEGV;
    }

    // ---- ticket: last CTA of this launch computes the KL loss ----
    __syncthreads();
    if (t == 0) {
        __threadfence();                        // release score store
        sTk = atomicAdd(&g_ticket, 1u);
    }
    __syncthreads();
    if (((sTk & 2047u) == 2047u) && w == 0) {
        __threadfence();                        // acquire all score stores
        float acc = 0.0f;
        for (int bb = lane; bb < B_; bb += 32) {
            float s[N_], tt[N_];
#pragma unroll
            for (int nn = 0; nn < N_; nn++) {
                s[nn]  = __ldcg(&g_scores[nn * B_ + bb]);
                tt[nn] = __ldcg(&g_scores[(N_ + nn) * B_ + bb]);
            }
            float ms = s[0], mt = tt[0];
#pragma unroll
            for (int nn = 1; nn < N_; nn++) { ms = fmaxf(ms, s[nn]); mt = fmaxf(mt, tt[nn]); }
            float es = 0.f, et = 0.f;
#pragma unroll
            for (int nn = 0; nn < N_; nn++) { es += expf(s[nn] - ms); et += expf(tt[nn] - mt); }
            float lses = ms + logf(es);
            float lset = mt + logf(et);
#pragma unroll
            for (int nn = 0; nn < N_; nn++) {
                float lt = tt[nn] - lset;
                float ls = s[nn]  - lses;
                acc += expf(lt) * (lt - ls);
            }
        }
#pragma unroll
        for (int o = 16; o; o >>= 1) acc += __shfl_xor_sync(~0u, acc, o);
        if (lane == 0) out[0] = acc / (float)B_;
    }
}

// ---------------------------------------------------------------------------
extern "C" void kernel_launch(void* const* d_in, const int* in_sizes, int n_in,
                              void* d_out, int out_size)
{
    const float* q     = (const float*)d_in[0];   // [B,Lq,D]
    const float* dcq   = (const float*)d_in[1];   // [N,B,Ld,D]
    const float* dorig = (const float*)d_in[2];   // [N,B,Ld,D]
    const int*   mask  = (const int*)d_in[3];     // [N,B,Ld]

    cudaFuncSetAttribute(maxsim_mma,
                         cudaFuncAttributeMaxDynamicSharedMemorySize, SMEM_TOTAL);
    dim3 grid(B_, N_, 2);
    maxsim_mma<<<grid, 256, SMEM_TOTAL>>>(q, dcq, dorig, mask, (float*)d_out);
}

// round 13
// speedup vs baseline: 1.5306x; 1.5306x over previous
#include <cuda_runtime.h>
#include <cstdint>
#include <math.h>

#define B_   128
#define N_   8
#define LQ   32
#define LD   256
#define D_   128
#define NEGV (-9999.0f)
#define STRD 132                       // padded row stride (floats): conflict-free frag loads

// ---- dynamic smem layout (bytes) ----
#define D0_OFF  0                       // D buf0: 32 rows x 132 floats = 16896
#define D1_OFF  16896                   // D buf1
#define QH_OFF  33792                   // Q hi tile: 32 x 132 floats (tf32-valued)
#define QL_OFF  50688                   // Q lo tile
#define INV_OFF 67584                   // 32 floats: per-row 1/||d|| (per chunk)
#define W_OFF   67712                   // 128 floats: per-warp query maxima
#define ACT_OFF 68224                   // 256 ints: compacted row ids
#define CNT_OFF 69248
#define SMEM_TOTAL 69264                // x3 CTA/SM = 207.8 KB < 228 KB

__device__ float g_scores[2 * N_ * B_];   // [z][n][b]
__device__ unsigned int g_ticket;         // wraps mod 2^32; 2048 per launch

__device__ __forceinline__ uint32_t smem_u32(const void* p) {
    uint32_t a;
    asm("{ .reg .u64 t; cvta.to.shared.u64 t, %1; cvt.u32.u64 %0, t; }" : "=r"(a) : "l"(p));
    return a;
}
__device__ __forceinline__ void cp16(uint32_t dst, const void* src) {
    asm volatile("cp.async.cg.shared.global [%0], [%1], 16;" :: "r"(dst), "l"(src));
}
__device__ __forceinline__ void cp_commit() { asm volatile("cp.async.commit_group;"); }
template<int NN> __device__ __forceinline__ void cp_wait() {
    asm volatile("cp.async.wait_group %0;" :: "n"(NN));
}
__device__ __forceinline__ uint32_t to_tf32(float f) {
    uint32_t r;
    asm("cvt.rna.tf32.f32 %0, %1;" : "=r"(r) : "f"(f));
    return r;
}
// m16n8k8 tf32 MMA (sm_80+ ISA; works on plain compute_100)
__device__ __forceinline__ void mma_tf32(float* c, const uint32_t* a,
                                         uint32_t b0, uint32_t b1) {
    asm volatile(
        "mma.sync.aligned.m16n8k8.row.col.f32.tf32.tf32.f32 "
        "{%0,%1,%2,%3}, {%4,%5,%6,%7}, {%8,%9}, {%0,%1,%2,%3};"
        : "+f"(c[0]), "+f"(c[1]), "+f"(c[2]), "+f"(c[3])
        : "r"(a[0]), "r"(a[1]), "r"(a[2]), "r"(a[3]), "r"(b0), "r"(b1));
}

// ---------------------------------------------------------------------------
// MaxSim + fused KL loss. grid (B, N, 2), 256 threads (8 warps), 3 CTAs/SM.
// 3xTF32 compensated MMA (Ah*Bh + Ah*Bl + Al*Bh); B split by exact bit
// truncation (LOP3+FSUB). 32-row chunks double-buffered (cp.async, wait<1>).
// 8 warps = 2 q-halves x 4 n-groups (1 n8 tile each). Mask compaction + tile
// skip. Last CTA (global ticket) computes KL(batchmean) — single launch.
// ---------------------------------------------------------------------------
__global__ void __launch_bounds__(256, 3)
maxsim_mma(const float* __restrict__ q, const float* __restrict__ dcq,
           const float* __restrict__ dorig, const int* __restrict__ mask,
           float* __restrict__ out)
{
    extern __shared__ __align__(16) char smem[];
    const uint32_t sbu = smem_u32(smem);
    float* sQh  = (float*)(smem + QH_OFF);
    float* sQl  = (float*)(smem + QL_OFF);
    float* sInv = (float*)(smem + INV_OFF);
    float* sW   = (float*)(smem + W_OFF);
    int*   sAct = (int*)(smem + ACT_OFF);
    int*   sCnt = (int*)(smem + CNT_OFF);
    __shared__ unsigned int sTk;

    const int b = blockIdx.x, n = blockIdx.y, z = blockIdx.z;
    const int t = threadIdx.x, lane = t & 31, w = t >> 5;
    const int wq = w & 1, ng = w >> 1;          // q-half; n-group (8 rows of chunk)
    const int g = lane >> 2, tg = lane & 3;
    const float* __restrict__ dpair = (z ? dorig : dcq) + (size_t)(n * B_ + b) * (LD * D_);

    if (t == 0) *sCnt = 0;

    // ---- stage Q: fp32 normalize, split hi/lo (cvt.rna, one-time) ----
    {
        const float4* qb = (const float4*)(q + (size_t)b * LQ * D_);
#pragma unroll
        for (int it = 0; it < 4; it++) {
            int row = it * 8 + w;
            float4 v = qb[row * 32 + lane];
            float ss = v.x * v.x + v.y * v.y + v.z * v.z + v.w * v.w;
#pragma unroll
            for (int o = 16; o; o >>= 1) ss += __shfl_xor_sync(~0u, ss, o);
            float inv = 1.0f / fmaxf(sqrtf(ss), 1e-12f);
            v.x *= inv; v.y *= inv; v.z *= inv; v.w *= inv;
            float4 hi, lo;
            hi.x = __uint_as_float(to_tf32(v.x)); lo.x = v.x - hi.x;
            hi.y = __uint_as_float(to_tf32(v.y)); lo.y = v.y - hi.y;
            hi.z = __uint_as_float(to_tf32(v.z)); lo.z = v.z - hi.z;
            hi.w = __uint_as_float(to_tf32(v.w)); lo.w = v.w - hi.w;
            *(float4*)(sQh + row * STRD + lane * 4) = hi;
            *(float4*)(sQl + row * STRD + lane * 4) = lo;
        }
    }
    __syncthreads();

    // ---- mask compaction (order irrelevant: max is commutative) ----
    if (mask[(n * B_ + b) * LD + t]) sAct[atomicAdd(sCnt, 1)] = t;
    __syncthreads();
    const int cnt = *sCnt;

    if (cnt > 0) {
        const int nch = (cnt + 31) >> 5;        // up to 8 chunks of 32 rows
        const int aoff = (16 * wq + g) * STRD + tg;
        const float* Ah = sQh + aoff;
        const float* Al = sQl + aoff;
        float mx0 = -1e30f, mx1 = -1e30f;

        auto load_chunk = [&](int ch) {
            uint32_t dstb = sbu + ((ch & 1) ? D1_OFF : D0_OFF);
#pragma unroll
            for (int it = 0; it < 4; it++) {
                int row = it * 8 + w;           // quad = lane
                int idx = ch * 32 + row; if (idx >= cnt) idx = cnt - 1;  // dup valid row
                cp16(dstb + (uint32_t)((row * STRD + lane * 4) * 4),
                     dpair + (size_t)sAct[idx] * D_ + lane * 4);
            }
        };

        load_chunk(0); cp_commit();

        for (int ch = 0; ch < nch; ch++) {
            if (ch + 1 < nch) { load_chunk(ch + 1); cp_commit(); cp_wait<1>(); }
            else             { cp_wait<0>(); }
            __syncthreads();                    // chunk ch resident; prev readers done

            float* Db = (float*)(smem + ((ch & 1) ? D1_OFF : D0_OFF));

            // ---- per-row inverse norms (fp32 exact): 4 rows per warp ----
#pragma unroll
            for (int rr = 0; rr < 4; rr++) {
                int row = rr * 8 + w;
                float4 v = *(const float4*)(Db + row * STRD + lane * 4);
                float ss = v.x * v.x + v.y * v.y + v.z * v.z + v.w * v.w;
#pragma unroll
                for (int o = 16; o; o >>= 1) ss += __shfl_xor_sync(~0u, ss, o);
                if (lane == 0) sInv[row] = 1.0f / fmaxf(sqrtf(ss), 1e-12f);
            }
            __syncthreads();

            // ---- this warp's n8 tile: chunk rows [8*ng, 8*ng+8) ----
            const int lcnt = min(cnt - ch * 32, 32);
            if (8 * ng < lcnt) {                // tile has at least one real row
                float acc[4] = {0.f, 0.f, 0.f, 0.f};
                const float* Brow = Db + (8 * ng + g) * STRD + tg;

#pragma unroll
                for (int s = 0; s < 16; s++) {
                    const int k0 = 8 * s;
                    uint32_t ah[4], al[4];
                    ah[0] = __float_as_uint(Ah[k0]);
                    ah[1] = __float_as_uint(Ah[8 * STRD + k0]);
                    ah[2] = __float_as_uint(Ah[k0 + 4]);
                    ah[3] = __float_as_uint(Ah[8 * STRD + k0 + 4]);
                    al[0] = __float_as_uint(Al[k0]);
                    al[1] = __float_as_uint(Al[8 * STRD + k0]);
                    al[2] = __float_as_uint(Al[k0 + 4]);
                    al[3] = __float_as_uint(Al[8 * STRD + k0 + 4]);

                    float b0 = Brow[k0], b1 = Brow[k0 + 4];
                    uint32_t b0h = __float_as_uint(b0) & 0xffffe000u;  // exact hi
                    uint32_t b1h = __float_as_uint(b1) & 0xffffe000u;
                    float b0l = b0 - __uint_as_float(b0h);             // exact lo
                    float b1l = b1 - __uint_as_float(b1h);
                    mma_tf32(acc, ah, b0h, b1h);
                    mma_tf32(acc, ah, __float_as_uint(b0l), __float_as_uint(b1l));
                    mma_tf32(acc, al, b0h, b1h);
                }

                // ---- scale by 1/||d||, fold into running per-query max ----
                float2 iv = *(const float2*)(sInv + 8 * ng + 2 * tg);
                mx0 = fmaxf(mx0, fmaxf(acc[0] * iv.x, acc[1] * iv.y));
                mx1 = fmaxf(mx1, fmaxf(acc[2] * iv.x, acc[3] * iv.y));
            }
            __syncthreads();                    // all reads of Db/sInv done
        }

        // ---- reduce: max over tg lanes, stage per-warp, combine, sum ----
        mx0 = fmaxf(mx0, __shfl_xor_sync(~0u, mx0, 1));
        mx0 = fmaxf(mx0, __shfl_xor_sync(~0u, mx0, 2));
        mx1 = fmaxf(mx1, __shfl_xor_sync(~0u, mx1, 1));
        mx1 = fmaxf(mx1, __shfl_xor_sync(~0u, mx1, 2));
        if (tg == 0) {
            sW[w * 16 + g]     = mx0;           // query 16*wq + g
            sW[w * 16 + 8 + g] = mx1;           // query +8
        }
        __syncthreads();
        if (t < 32) {
            int wq2 = t >> 4, m = t & 15;       // query t = 16*wq2 + m
            float v = fmaxf(fmaxf(sW[wq2 * 16 + m],       sW[(2 + wq2) * 16 + m]),
                            fmaxf(sW[(4 + wq2) * 16 + m], sW[(6 + wq2) * 16 + m]));
#pragma unroll
            for (int o = 16; o; o >>= 1) v += __shfl_xor_sync(~0u, v, o);
            if (t == 0) g_scores[(z * N_ + n) * B_ + b] = v;
        }
    } else if (t == 0) {                        // all masked: scores = 32 * NEG
        g_scores[(z * N_ + n) * B_ + b] = 32.0f * NEGV;
    }

    // ---- ticket: last CTA of this launch computes the KL loss ----
    __syncthreads();
    if (t == 0) {
        __threadfence();                        // release score store
        sTk = atomicAdd(&g_ticket, 1u);
    }
    __syncthreads();
    if (((sTk & 2047u) == 2047u) && w == 0) {
        __threadfence();                        // acquire all score stores
        float acc = 0.0f;
        for (int bb = lane; bb < B_; bb += 32) {
            float s[N_], tt[N_];
#pragma unroll
            for (int nn = 0; nn < N_; nn++) {
                s[nn]  = __ldcg(&g_scores[nn * B_ + bb]);
                tt[nn] = __ldcg(&g_scores[(N_ + nn) * B_ + bb]);
            }
            float ms = s[0], mt = tt[0];
#pragma unroll
            for (int nn = 1; nn < N_; nn++) { ms = fmaxf(ms, s[nn]); mt = fmaxf(mt, tt[nn]); }
            float es = 0.f, et = 0.f;
#pragma unroll
            for (int nn = 0; nn < N_; nn++) { es += expf(s[nn] - ms); et += expf(tt[nn] - mt); }
            float lses = ms + logf(es);
            float lset = mt + logf(et);
#pragma unroll
            for (int nn = 0; nn < N_; nn++) {
                float lt = tt[nn] - lset;
                float ls = s[nn]  - lses;
                acc += expf(lt) * (lt - ls);
            }
        }
#pragma unroll
        for (int o = 16; o; o >>= 1) acc += __shfl_xor_sync(~0u, acc, o);
        if (lane == 0) out[0] = acc / (float)B_;
    }
}

// ---------------------------------------------------------------------------
extern "C" void kernel_launch(void* const* d_in, const int* in_sizes, int n_in,
                              void* d_out, int out_size)
{
    const float* q     = (const float*)d_in[0];   // [B,Lq,D]
    const float* dcq   = (const float*)d_in[1];   // [N,B,Ld,D]
    const float* dorig = (const float*)d_in[2];   // [N,B,Ld,D]
    const int*   mask  = (const int*)d_in[3];     // [N,B,Ld]

    cudaFuncSetAttribute(maxsim_mma,
                         cudaFuncAttributeMaxDynamicSharedMemorySize, SMEM_TOTAL);
    dim3 grid(B_, N_, 2);
    maxsim_mma<<<grid, 256, SMEM_TOTAL>>>(q, dcq, dorig, mask, (float*)d_out);
}

// round 14
// speedup vs baseline: 1.6316x; 1.0660x over previous
#include <cuda_runtime.h>
#include <cstdint>
#include <math.h>

#define B_   128
#define N_   8
#define LQ   32
#define LD   256
#define D_   128
#define NEGV (-9999.0f)
#define STRD 132                       // padded row stride (floats): conflict-free frag loads

// ---- dynamic smem layout (bytes) ----
#define D0_OFF   0                      // D buf0: 32 rows x 132 floats = 16896
#define D1_OFF   16896                  // D buf1
#define QH_OFF   33792                  // Q hi tile: 32 x 132 floats (tf32-valued)
#define QL_OFF   50688                  // Q lo tile
#define INV_OFF  67584                  // 32 floats: per-row 1/||d|| (per chunk)
#define W_OFF    67712                  // 64 floats: per-(rg,qh) query maxima
#define ACT_OFF  67968                  // 256 ints: compacted row ids
#define CNT_OFF  68992
#define COMB_OFF 69008                  // k-combine: 4 pairs x 8 regs x 32 lanes = 4096
#define SMEM_TOTAL 73104                // x3 CTA/SM = 219.3 KB < 228 KB

__device__ float g_scores[2 * N_ * B_];   // [z][n][b]
__device__ unsigned int g_ticket;         // wraps mod 2^32; 2048 per launch

__device__ __forceinline__ uint32_t smem_u32(const void* p) {
    uint32_t a;
    asm("{ .reg .u64 t; cvta.to.shared.u64 t, %1; cvt.u32.u64 %0, t; }" : "=r"(a) : "l"(p));
    return a;
}
__device__ __forceinline__ void cp16(uint32_t dst, const void* src) {
    asm volatile("cp.async.cg.shared.global [%0], [%1], 16;" :: "r"(dst), "l"(src));
}
__device__ __forceinline__ void cp_commit() { asm volatile("cp.async.commit_group;"); }
template<int NN> __device__ __forceinline__ void cp_wait() {
    asm volatile("cp.async.wait_group %0;" :: "n"(NN));
}
__device__ __forceinline__ uint32_t to_tf32(float f) {
    uint32_t r;
    asm("cvt.rna.tf32.f32 %0, %1;" : "=r"(r) : "f"(f));
    return r;
}
// m16n8k8 tf32 MMA (sm_80+ ISA; works on plain compute_100)
__device__ __forceinline__ void mma_tf32(float* c, const uint32_t* a,
                                         uint32_t b0, uint32_t b1) {
    asm volatile(
        "mma.sync.aligned.m16n8k8.row.col.f32.tf32.tf32.f32 "
        "{%0,%1,%2,%3}, {%4,%5,%6,%7}, {%8,%9}, {%0,%1,%2,%3};"
        : "+f"(c[0]), "+f"(c[1]), "+f"(c[2]), "+f"(c[3])
        : "r"(a[0]), "r"(a[1]), "r"(a[2]), "r"(a[3]), "r"(b0), "r"(b1));
}

// ---------------------------------------------------------------------------
// MaxSim + fused KL loss. grid (B, N, 2), 256 threads (8 warps), 3 CTAs/SM.
// Operands swapped vs R13: A = D rows (m16, raw + in-register split),
// B = Q (n8, pre-split hi/lo) -> ~1.9x less LDS per MAC.
// 8 warps = 2 row-groups x 2 q-halves x 2 k-halves; k-halves combined via
// smem per chunk. 3xTF32 compensated (Dh*Qh + Dh*Ql + Dl*Qh). 32-row chunks
// double-buffered (cp.async). Ticket: last CTA computes KL(batchmean).
// ---------------------------------------------------------------------------
__global__ void __launch_bounds__(256, 3)
maxsim_mma(const float* __restrict__ q, const float* __restrict__ dcq,
           const float* __restrict__ dorig, const int* __restrict__ mask,
           float* __restrict__ out)
{
    extern __shared__ __align__(16) char smem[];
    const uint32_t sbu = smem_u32(smem);
    float* sQh  = (float*)(smem + QH_OFF);
    float* sQl  = (float*)(smem + QL_OFF);
    float* sInv = (float*)(smem + INV_OFF);
    float* sW   = (float*)(smem + W_OFF);
    int*   sAct = (int*)(smem + ACT_OFF);
    int*   sCnt = (int*)(smem + CNT_OFF);
    float* sCmb = (float*)(smem + COMB_OFF);
    __shared__ unsigned int sTk;

    const int b = blockIdx.x, n = blockIdx.y, z = blockIdx.z;
    const int t = threadIdx.x, lane = t & 31, w = t >> 5;
    const int qh = w & 1, rg = (w >> 1) & 1, kh = w >> 2;
    const int pair = rg * 2 + qh;               // 0..3
    const int g = lane >> 2, tg = lane & 3;
    const float* __restrict__ dpair = (z ? dorig : dcq) + (size_t)(n * B_ + b) * (LD * D_);

    if (t == 0) *sCnt = 0;

    // ---- stage Q: fp32 normalize, split hi/lo (cvt.rna + exact residual) ----
    {
        const float4* qb = (const float4*)(q + (size_t)b * LQ * D_);
#pragma unroll
        for (int it = 0; it < 4; it++) {
            int row = it * 8 + w;
            float4 v = qb[row * 32 + lane];
            float ss = v.x * v.x + v.y * v.y + v.z * v.z + v.w * v.w;
#pragma unroll
            for (int o = 16; o; o >>= 1) ss += __shfl_xor_sync(~0u, ss, o);
            float inv = 1.0f / fmaxf(sqrtf(ss), 1e-12f);
            v.x *= inv; v.y *= inv; v.z *= inv; v.w *= inv;
            float4 hi, lo;
            hi.x = __uint_as_float(to_tf32(v.x)); lo.x = v.x - hi.x;
            hi.y = __uint_as_float(to_tf32(v.y)); lo.y = v.y - hi.y;
            hi.z = __uint_as_float(to_tf32(v.z)); lo.z = v.z - hi.z;
            hi.w = __uint_as_float(to_tf32(v.w)); lo.w = v.w - hi.w;
            *(float4*)(sQh + row * STRD + lane * 4) = hi;
            *(float4*)(sQl + row * STRD + lane * 4) = lo;
        }
    }
    __syncthreads();

    // ---- mask compaction (order irrelevant: max is commutative) ----
    if (mask[(n * B_ + b) * LD + t]) sAct[atomicAdd(sCnt, 1)] = t;
    __syncthreads();
    const int cnt = *sCnt;

    if (cnt > 0) {
        const int nch = (cnt + 31) >> 5;        // up to 8 chunks of 32 rows
        // B fragments: Q tile j covers queries 16*qh + 8j + g
        const int qoff0 = (16 * qh + g) * STRD + tg;
        const int qoff1 = qoff0 + 8 * STRD;
        // running per-query max: mx[j][e] for query 16qh + 8j + 2tg + e
        float mx[2][2] = {{-1e30f, -1e30f}, {-1e30f, -1e30f}};

        auto load_chunk = [&](int ch) {
            uint32_t dstb = sbu + ((ch & 1) ? D1_OFF : D0_OFF);
#pragma unroll
            for (int it = 0; it < 4; it++) {
                int row = it * 8 + w;           // quad = lane
                int idx = ch * 32 + row; if (idx >= cnt) idx = cnt - 1;  // dup valid row
                cp16(dstb + (uint32_t)((row * STRD + lane * 4) * 4),
                     dpair + (size_t)sAct[idx] * D_ + lane * 4);
            }
        };

        load_chunk(0); cp_commit();

        for (int ch = 0; ch < nch; ch++) {
            if (ch + 1 < nch) { load_chunk(ch + 1); cp_commit(); cp_wait<1>(); }
            else             { cp_wait<0>(); }
            __syncthreads();                    // chunk ch resident; prev readers done

            float* Db = (float*)(smem + ((ch & 1) ? D1_OFF : D0_OFF));

            // ---- per-row inverse norms (fp32 exact): 4 rows per warp ----
#pragma unroll
            for (int rr = 0; rr < 4; rr++) {
                int row = rr * 8 + w;
                float4 v = *(const float4*)(Db + row * STRD + lane * 4);
                float ss = v.x * v.x + v.y * v.y + v.z * v.z + v.w * v.w;
#pragma unroll
                for (int o = 16; o; o >>= 1) ss += __shfl_xor_sync(~0u, ss, o);
                if (lane == 0) sInv[row] = 1.0f / fmaxf(sqrtf(ss), 1e-12f);
            }
            __syncthreads();

            const int lcnt = min(cnt - ch * 32, 32);
            const bool active = (16 * rg < lcnt);
            float acc[2][4] = {{0.f,0.f,0.f,0.f},{0.f,0.f,0.f,0.f}};

            if (active) {
                // A = D rows [16*rg, 16*rg+16); this warp's k-half
                const float* Drow = Db + (16 * rg + g) * STRD + tg;
#pragma unroll
                for (int s = 0; s < 8; s++) {
                    const int k0 = 64 * kh + 8 * s;
                    float d0 = Drow[k0];
                    float d1 = Drow[8 * STRD + k0];
                    float d2 = Drow[k0 + 4];
                    float d3 = Drow[8 * STRD + k0 + 4];
                    uint32_t ah[4], al[4];
                    ah[0] = __float_as_uint(d0) & 0xffffe000u;
                    ah[1] = __float_as_uint(d1) & 0xffffe000u;
                    ah[2] = __float_as_uint(d2) & 0xffffe000u;
                    ah[3] = __float_as_uint(d3) & 0xffffe000u;
                    al[0] = __float_as_uint(d0 - __uint_as_float(ah[0]));
                    al[1] = __float_as_uint(d1 - __uint_as_float(ah[1]));
                    al[2] = __float_as_uint(d2 - __uint_as_float(ah[2]));
                    al[3] = __float_as_uint(d3 - __uint_as_float(ah[3]));

                    // tile 0: queries 16qh..+8
                    {
                        uint32_t bh0 = __float_as_uint(sQh[qoff0 + k0]);
                        uint32_t bh1 = __float_as_uint(sQh[qoff0 + k0 + 4]);
                        uint32_t bl0 = __float_as_uint(sQl[qoff0 + k0]);
                        uint32_t bl1 = __float_as_uint(sQl[qoff0 + k0 + 4]);
                        mma_tf32(acc[0], ah, bh0, bh1);
                        mma_tf32(acc[0], ah, bl0, bl1);
                        mma_tf32(acc[0], al, bh0, bh1);
                    }
                    // tile 1: queries 16qh+8..+16
                    {
                        uint32_t bh0 = __float_as_uint(sQh[qoff1 + k0]);
                        uint32_t bh1 = __float_as_uint(sQh[qoff1 + k0 + 4]);
                        uint32_t bl0 = __float_as_uint(sQl[qoff1 + k0]);
                        uint32_t bl1 = __float_as_uint(sQl[qoff1 + k0 + 4]);
                        mma_tf32(acc[1], ah, bh0, bh1);
                        mma_tf32(acc[1], ah, bl0, bl1);
                        mma_tf32(acc[1], al, bh0, bh1);
                    }
                }
            }

            // ---- combine k-halves via smem (scalar layout, conflict-free) ----
            if (kh == 1 && active) {
#pragma unroll
                for (int r = 0; r < 8; r++)
                    sCmb[(pair * 8 + r) * 32 + lane] = acc[r >> 2][r & 3];
            }
            __syncthreads();
            if (kh == 0 && active) {
                float ivg  = sInv[16 * rg + g];
                float ivg8 = sInv[16 * rg + g + 8];
#pragma unroll
                for (int j = 0; j < 2; j++) {
                    float c0 = acc[j][0] + sCmb[(pair * 8 + j * 4 + 0) * 32 + lane];
                    float c1 = acc[j][1] + sCmb[(pair * 8 + j * 4 + 1) * 32 + lane];
                    float c2 = acc[j][2] + sCmb[(pair * 8 + j * 4 + 2) * 32 + lane];
                    float c3 = acc[j][3] + sCmb[(pair * 8 + j * 4 + 3) * 32 + lane];
                    // C rows = D rows (g, g+8); cols = queries 8j+2tg, +1
                    mx[j][0] = fmaxf(mx[j][0], fmaxf(c0 * ivg, c2 * ivg8));
                    mx[j][1] = fmaxf(mx[j][1], fmaxf(c1 * ivg, c3 * ivg8));
                }
            }
            __syncthreads();                    // Db/sInv/sCmb reuse safe
        }

        // ---- reduce: kh==0 warps hold per-(g)-partial query maxima ----
        if (kh == 0) {
#pragma unroll
            for (int j = 0; j < 2; j++)
#pragma unroll
                for (int e = 0; e < 2; e++) {
                    float v = mx[j][e];
                    v = fmaxf(v, __shfl_xor_sync(~0u, v, 4));
                    v = fmaxf(v, __shfl_xor_sync(~0u, v, 8));
                    v = fmaxf(v, __shfl_xor_sync(~0u, v, 16));
                    mx[j][e] = v;
                }
            if (lane < 4) {                     // tg = lane, g = 0
#pragma unroll
                for (int j = 0; j < 2; j++) {
                    sW[pair * 16 + 8 * j + 2 * lane]     = mx[j][0];
                    sW[pair * 16 + 8 * j + 2 * lane + 1] = mx[j][1];
                }
            }
        }
        __syncthreads();
        if (t < 32) {
            int qh2 = t >> 4, m = t & 15;       // query t = 16*qh2 + m
            float v = fmaxf(sW[(0 * 2 + qh2) * 16 + m], sW[(1 * 2 + qh2) * 16 + m]);
#pragma unroll
            for (int o = 16; o; o >>= 1) v += __shfl_xor_sync(~0u, v, o);
            if (t == 0) g_scores[(z * N_ + n) * B_ + b] = v;
        }
    } else if (t == 0) {                        // all masked: scores = 32 * NEG
        g_scores[(z * N_ + n) * B_ + b] = 32.0f * NEGV;
    }

    // ---- ticket: last CTA of this launch computes the KL loss ----
    __syncthreads();
    if (t == 0) {
        __threadfence();                        // release score store
        sTk = atomicAdd(&g_ticket, 1u);
    }
    __syncthreads();
    if (((sTk & 2047u) == 2047u) && w == 0) {
        __threadfence();                        // acquire all score stores
        float acc = 0.0f;
        for (int bb = lane; bb < B_; bb += 32) {
            float s[N_], tt[N_];
#pragma unroll
            for (int nn = 0; nn < N_; nn++) {
                s[nn]  = __ldcg(&g_scores[nn * B_ + bb]);
                tt[nn] = __ldcg(&g_scores[(N_ + nn) * B_ + bb]);
            }
            float ms = s[0], mt = tt[0];
#pragma unroll
            for (int nn = 1; nn < N_; nn++) { ms = fmaxf(ms, s[nn]); mt = fmaxf(mt, tt[nn]); }
            float es = 0.f, et = 0.f;
#pragma unroll
            for (int nn = 0; nn < N_; nn++) { es += expf(s[nn] - ms); et += expf(tt[nn] - mt); }
            float lses = ms + logf(es);
            float lset = mt + logf(et);
#pragma unroll
            for (int nn = 0; nn < N_; nn++) {
                float lt = tt[nn] - lset;
                float ls = s[nn]  - lses;
                acc += expf(lt) * (lt - ls);
            }
        }
#pragma unroll
        for (int o = 16; o; o >>= 1) acc += __shfl_xor_sync(~0u, acc, o);
        if (lane == 0) out[0] = acc / (float)B_;
    }
}

// ---------------------------------------------------------------------------
extern "C" void kernel_launch(void* const* d_in, const int* in_sizes, int n_in,
                              void* d_out, int out_size)
{
    const float* q     = (const float*)d_in[0];   // [B,Lq,D]
    const float* dcq   = (const float*)d_in[1];   // [N,B,Ld,D]
    const float* dorig = (const float*)d_in[2];   // [N,B,Ld,D]
    const int*   mask  = (const int*)d_in[3];     // [N,B,Ld]

    cudaFuncSetAttribute(maxsim_mma,
                         cudaFuncAttributeMaxDynamicSharedMemorySize, SMEM_TOTAL);
    dim3 grid(B_, N_, 2);
    maxsim_mma<<<grid, 256, SMEM_TOTAL>>>(q, dcq, dorig, mask, (float*)d_out);
}

// round 17
// speedup vs baseline: 1.8157x; 1.1128x over previous
#include <cuda_runtime.h>
#include <cstdint>
#include <math.h>

#define B_   128
#define N_   8
#define LQ   32
#define LD   256
#define D_   128
#define NEGV (-9999.0f)
#define STRD 132                       // padded row stride (floats): conflict-free frag loads

// ---- dynamic smem layout (bytes) ----
#define D0_OFF   0                      // D buf0: 32 rows x 132 floats = 16896
#define D1_OFF   16896                  // D buf1
#define Q_OFF    33792                  // Q tile: 32 x 132 floats (normalized fp32)
#define INV_OFF  50688                  // 32 floats: per-row 1/||d|| (per chunk)
#define W_OFF    50816                  // 64 floats: per-(rg,qh) query maxima
#define ACT_OFF  51072                  // 256 ints: compacted row ids
#define CNT_OFF  52096
#define COMB_OFF 52112                  // k-combine: 4 pairs x 8 regs x 32 lanes = 4096
#define SMEM_TOTAL 56208                // x4 CTA/SM = 224.8 KB < 228 KB

__device__ float g_scores[2 * N_ * B_];   // [z][n][b]
__device__ unsigned int g_ticket;         // wraps mod 2^32; 2048 per launch

__device__ __forceinline__ uint32_t smem_u32(const void* p) {
    uint32_t a;
    asm("{ .reg .u64 t; cvta.to.shared.u64 t, %1; cvt.u32.u64 %0, t; }" : "=r"(a) : "l"(p));
    return a;
}
__device__ __forceinline__ void cp16(uint32_t dst, const void* src) {
    asm volatile("cp.async.cg.shared.global [%0], [%1], 16;" :: "r"(dst), "l"(src));
}
__device__ __forceinline__ void cp_commit() { asm volatile("cp.async.commit_group;"); }
template<int NN> __device__ __forceinline__ void cp_wait() {
    asm volatile("cp.async.wait_group %0;" :: "n"(NN));
}
// m16n8k8 tf32 MMA (sm_80+ ISA; works on plain compute_100)
__device__ __forceinline__ void mma_tf32(float* c, const uint32_t* a,
                                         uint32_t b0, uint32_t b1) {
    asm volatile(
        "mma.sync.aligned.m16n8k8.row.col.f32.tf32.tf32.f32 "
        "{%0,%1,%2,%3}, {%4,%5,%6,%7}, {%8,%9}, {%0,%1,%2,%3};"
        : "+f"(c[0]), "+f"(c[1]), "+f"(c[2]), "+f"(c[3])
        : "r"(a[0]), "r"(a[1]), "r"(a[2]), "r"(a[3]), "r"(b0), "r"(b1));
}
// exact split: hi = trunc-to-tf32(x) (mask), lo = x - hi (exact in fp32)
__device__ __forceinline__ void split2(float x, uint32_t& hi, uint32_t& lo) {
    hi = __float_as_uint(x) & 0xffffe000u;
    lo = __float_as_uint(x - __uint_as_float(hi));
}

// ---------------------------------------------------------------------------
// MaxSim + fused KL loss. grid (B, N, 2), 256 threads (8 warps), 4 CTAs/SM.
// A = D rows (m16, raw, in-register split); B = Q (n8, raw, in-register
// split) — single fp32 Q tile in smem (no pre-split tiles) buys the 4th CTA.
// 8 warps = 2 row-groups x 2 q-halves x 2 k-halves; k-halves combined via
// smem per chunk. 3xTF32 compensated (Dh*Qh + Dh*Ql + Dl*Qh). 32-row chunks
// double-buffered (cp.async). Ticket: last CTA computes KL(batchmean).
// No early returns: every thread reaches every barrier (hang-proof).
// ---------------------------------------------------------------------------
__global__ void __launch_bounds__(256, 4)
maxsim_mma(const float* __restrict__ q, const float* __restrict__ dcq,
           const float* __restrict__ dorig, const int* __restrict__ mask,
           float* __restrict__ out)
{
    extern __shared__ __align__(16) char smem[];
    const uint32_t sbu = smem_u32(smem);
    float* sQ   = (float*)(smem + Q_OFF);
    float* sInv = (float*)(smem + INV_OFF);
    float* sW   = (float*)(smem + W_OFF);
    int*   sAct = (int*)(smem + ACT_OFF);
    int*   sCnt = (int*)(smem + CNT_OFF);
    float* sCmb = (float*)(smem + COMB_OFF);
    __shared__ unsigned int sTk;

    const int b = blockIdx.x, n = blockIdx.y, z = blockIdx.z;
    const int t = threadIdx.x, lane = t & 31, w = t >> 5;
    const int qh = w & 1, rg = (w >> 1) & 1, kh = w >> 2;
    const int pair = rg * 2 + qh;               // 0..3
    const int g = lane >> 2, tg = lane & 3;
    const float* __restrict__ dpair = (z ? dorig : dcq) + (size_t)(n * B_ + b) * (LD * D_);

    if (t == 0) *sCnt = 0;

    // ---- stage Q: fp32 normalize (split happens in-register later) ----
    {
        const float4* qb = (const float4*)(q + (size_t)b * LQ * D_);
#pragma unroll
        for (int it = 0; it < 4; it++) {
            int row = it * 8 + w;
            float4 v = qb[row * 32 + lane];
            float ss = v.x * v.x + v.y * v.y + v.z * v.z + v.w * v.w;
#pragma unroll
            for (int o = 16; o; o >>= 1) ss += __shfl_xor_sync(~0u, ss, o);
            float inv = 1.0f / fmaxf(sqrtf(ss), 1e-12f);
            *(float4*)(sQ + row * STRD + lane * 4) =
                make_float4(v.x * inv, v.y * inv, v.z * inv, v.w * inv);
        }
    }
    __syncthreads();

    // ---- mask compaction (order irrelevant: max is commutative) ----
    if (mask[(n * B_ + b) * LD + t]) sAct[atomicAdd(sCnt, 1)] = t;
    __syncthreads();
    const int cnt = *sCnt;

    if (cnt > 0) {
        const int nch = (cnt + 31) >> 5;        // up to 8 chunks of 32 rows
        const int qoff0 = (16 * qh + g) * STRD + tg;    // Q tile 0: queries 16qh+g..
        const int qoff1 = qoff0 + 8 * STRD;             // Q tile 1: +8
        // running per-query max: mx[j][e] for query 16qh + 8j + 2tg + e
        float mx[2][2] = {{-1e30f, -1e30f}, {-1e30f, -1e30f}};

        auto load_chunk = [&](int ch) {
            uint32_t dstb = sbu + ((ch & 1) ? D1_OFF : D0_OFF);
#pragma unroll
            for (int it = 0; it < 4; it++) {
                int row = it * 8 + w;           // quad = lane
                int idx = ch * 32 + row; if (idx >= cnt) idx = cnt - 1;  // dup valid row
                cp16(dstb + (uint32_t)((row * STRD + lane * 4) * 4),
                     dpair + (size_t)sAct[idx] * D_ + lane * 4);
            }
        };

        load_chunk(0); cp_commit();

        for (int ch = 0; ch < nch; ch++) {
            if (ch + 1 < nch) { load_chunk(ch + 1); cp_commit(); cp_wait<1>(); }
            else             { cp_wait<0>(); }
            __syncthreads();                    // chunk ch resident; prev readers done

            float* Db = (float*)(smem + ((ch & 1) ? D1_OFF : D0_OFF));

            // ---- per-row inverse norms (fp32 exact): 4 rows per warp ----
#pragma unroll
            for (int rr = 0; rr < 4; rr++) {
                int row = rr * 8 + w;
                float4 v = *(const float4*)(Db + row * STRD + lane * 4);
                float ss = v.x * v.x + v.y * v.y + v.z * v.z + v.w * v.w;
#pragma unroll
                for (int o = 16; o; o >>= 1) ss += __shfl_xor_sync(~0u, ss, o);
                if (lane == 0) sInv[row] = 1.0f / fmaxf(sqrtf(ss), 1e-12f);
            }
            __syncthreads();

            const int lcnt = min(cnt - ch * 32, 32);
            const bool active = (16 * rg < lcnt);
            float acc[2][4] = {{0.f,0.f,0.f,0.f},{0.f,0.f,0.f,0.f}};

            if (active) {
                // A = D rows [16*rg, 16*rg+16); this warp's k-half
                const float* Drow = Db + (16 * rg + g) * STRD + tg;
#pragma unroll
                for (int s = 0; s < 8; s++) {
                    const int k0 = 64 * kh + 8 * s;
                    uint32_t ah[4], al[4];
                    split2(Drow[k0],            ah[0], al[0]);
                    split2(Drow[8 * STRD + k0], ah[1], al[1]);
                    split2(Drow[k0 + 4],        ah[2], al[2]);
                    split2(Drow[8 * STRD + k0 + 4], ah[3], al[3]);

                    // tile 0: queries 16qh..+8
                    {
                        uint32_t bh0, bl0, bh1, bl1;
                        split2(sQ[qoff0 + k0],     bh0, bl0);
                        split2(sQ[qoff0 + k0 + 4], bh1, bl1);
                        mma_tf32(acc[0], ah, bh0, bh1);
                        mma_tf32(acc[0], ah, bl0, bl1);
                        mma_tf32(acc[0], al, bh0, bh1);
                    }
                    // tile 1: queries 16qh+8..+16
                    {
                        uint32_t bh0, bl0, bh1, bl1;
                        split2(sQ[qoff1 + k0],     bh0, bl0);
                        split2(sQ[qoff1 + k0 + 4], bh1, bl1);
                        mma_tf32(acc[1], ah, bh0, bh1);
                        mma_tf32(acc[1], ah, bl0, bl1);
                        mma_tf32(acc[1], al, bh0, bh1);
                    }
                }
            }

            // ---- combine k-halves via smem (scalar layout, conflict-free) ----
            if (kh == 1 && active) {
#pragma unroll
                for (int r = 0; r < 8; r++)
                    sCmb[(pair * 8 + r) * 32 + lane] = acc[r >> 2][r & 3];
            }
            __syncthreads();
            if (kh == 0 && active) {
                float ivg  = sInv[16 * rg + g];
                float ivg8 = sInv[16 * rg + g + 8];
#pragma unroll
                for (int j = 0; j < 2; j++) {
                    float c0 = acc[j][0] + sCmb[(pair * 8 + j * 4 + 0) * 32 + lane];
                    float c1 = acc[j][1] + sCmb[(pair * 8 + j * 4 + 1) * 32 + lane];
                    float c2 = acc[j][2] + sCmb[(pair * 8 + j * 4 + 2) * 32 + lane];
                    float c3 = acc[j][3] + sCmb[(pair * 8 + j * 4 + 3) * 32 + lane];
                    // C rows = D rows (g, g+8); cols = queries 8j+2tg, +1
                    mx[j][0] = fmaxf(mx[j][0], fmaxf(c0 * ivg, c2 * ivg8));
                    mx[j][1] = fmaxf(mx[j][1], fmaxf(c1 * ivg, c3 * ivg8));
                }
            }
            __syncthreads();                    // Db/sInv/sCmb reuse safe
        }

        // ---- reduce: kh==0 warps hold per-(g)-partial query maxima ----
        if (kh == 0) {
#pragma unroll
            for (int j = 0; j < 2; j++)
#pragma unroll
                for (int e = 0; e < 2; e++) {
                    float v = mx[j][e];
                    v = fmaxf(v, __shfl_xor_sync(~0u, v, 4));
                    v = fmaxf(v, __shfl_xor_sync(~0u, v, 8));
                    v = fmaxf(v, __shfl_xor_sync(~0u, v, 16));
                    mx[j][e] = v;
                }
            if (lane < 4) {                     // tg = lane, g = 0
#pragma unroll
                for (int j = 0; j < 2; j++) {
                    sW[pair * 16 + 8 * j + 2 * lane]     = mx[j][0];
                    sW[pair * 16 + 8 * j + 2 * lane + 1] = mx[j][1];
                }
            }
        }
        __syncthreads();
        if (t < 32) {
            int qh2 = t >> 4, m = t & 15;       // query t = 16*qh2 + m
            float v = fmaxf(sW[(0 * 2 + qh2) * 16 + m], sW[(1 * 2 + qh2) * 16 + m]);
#pragma unroll
            for (int o = 16; o; o >>= 1) v += __shfl_xor_sync(~0u, v, o);
            if (t == 0) g_scores[(z * N_ + n) * B_ + b] = v;
        }
    } else if (t == 0) {                        // all masked: scores = 32 * NEG
        g_scores[(z * N_ + n) * B_ + b] = 32.0f * NEGV;
    }

    // ---- ticket: last CTA of this launch computes the KL loss ----
    __syncthreads();
    if (t == 0) {
        __threadfence();                        // release score store
        sTk = atomicAdd(&g_ticket, 1u);
    }
    __syncthreads();
    if (((sTk & 2047u) == 2047u) && w == 0) {
        __threadfence();                        // acquire all score stores
        float acc = 0.0f;
        for (int bb = lane; bb < B_; bb += 32) {
            float s[N_], tt[N_];
#pragma unroll
            for (int nn = 0; nn < N_; nn++) {
                s[nn]  = __ldcg(&g_scores[nn * B_ + bb]);
                tt[nn] = __ldcg(&g_scores[(N_ + nn) * B_ + bb]);
            }
            float ms = s[0], mt = tt[0];
#pragma unroll
            for (int nn = 1; nn < N_; nn++) { ms = fmaxf(ms, s[nn]); mt = fmaxf(mt, tt[nn]); }
            float es = 0.f, et = 0.f;
#pragma unroll
            for (int nn = 0; nn < N_; nn++) { es += expf(s[nn] - ms); et += expf(tt[nn] - mt); }
            float lses = ms + logf(es);
            float lset = mt + logf(et);
#pragma unroll
            for (int nn = 0; nn < N_; nn++) {
                float lt = tt[nn] - lset;
                float ls = s[nn]  - lses;
                acc += expf(lt) * (lt - ls);
            }
        }
#pragma unroll
        for (int o = 16; o; o >>= 1) acc += __shfl_xor_sync(~0u, acc, o);
        if (lane == 0) out[0] = acc / (float)B_;
    }
}

// ---------------------------------------------------------------------------
extern "C" void kernel_launch(void* const* d_in, const int* in_sizes, int n_in,
                              void* d_out, int out_size)
{
    const float* q     = (const float*)d_in[0];   // [B,Lq,D]
    const float* dcq   = (const float*)d_in[1];   // [N,B,Ld,D]
    const float* dorig = (const float*)d_in[2];   // [N,B,Ld,D]
    const int*   mask  = (const int*)d_in[3];     // [N,B,Ld]

    cudaFuncSetAttribute(maxsim_mma,
                         cudaFuncAttributeMaxDynamicSharedMemorySize, SMEM_TOTAL);
    dim3 grid(B_, N_, 2);
    maxsim_mma<<<grid, 256, SMEM_TOTAL>>>(q, dcq, dorig, mask, (float*)d_out);
}